// round 15
// baseline (speedup 1.0000x reference)
#include <cuda_runtime.h>
#include <cuda_bf16.h>
#include <cstdint>

#define SEQ 2048
#define DIN 2048
#define NH 32
#define NKV 8
#define HD 128
#define QDIM 4096
#define KVDIM 1024
#define QKV (QDIM + 2 * KVDIM)   // 6144

typedef __nv_bfloat16 bf16;
typedef __nv_bfloat162 bf162;

#define BM 128
#define BN 128
#define BK 32

// ---------------- static scratch (no allocs allowed) ----------------
__device__ bf16 g_xhi[(size_t)SEQ * DIN];
__device__ bf16 g_xlo[(size_t)SEQ * DIN];
__device__ bf16 g_Wqkvh[(size_t)QKV * DIN], g_Wqkvl[(size_t)QKV * DIN];
__device__ bf16 g_Woh[(size_t)DIN * QDIM],  g_Wol[(size_t)DIN * QDIM];
__device__ float g_QKVp[(size_t)SEQ * QKV];
__device__ bf16 g_Qhi[(size_t)SEQ * QDIM], g_Qlo[(size_t)SEQ * QDIM];
__device__ bf16 g_Khi[(size_t)NKV * SEQ * HD], g_Klo[(size_t)NKV * SEQ * HD];
__device__ bf16 g_Vthi[(size_t)NKV * HD * SEQ], g_Vtlo[(size_t)NKV * HD * SEQ];
__device__ bf16 g_ctxh[(size_t)SEQ * QDIM], g_ctxl[(size_t)SEQ * QDIM];

// ---------------- helpers ----------------
__device__ __forceinline__ uint32_t smem_u32(const void* p) {
    uint32_t a;
    asm("{ .reg .u64 t; cvta.to.shared.u64 t, %1; cvt.u32.u64 %0, t; }" : "=r"(a) : "l"(p));
    return a;
}
#define SWZ64(o) ((o) ^ ((((o) >> 7) & 3u) << 4))

#define CP16(dst, src) asm volatile("cp.async.cg.shared.global [%0], [%1], 16;" :: "r"(dst), "l"(src))
#define CP_COMMIT()    asm volatile("cp.async.commit_group;" ::: "memory")
#define CP_WAIT1()     asm volatile("cp.async.wait_group 1;" ::: "memory")
#define CP_WAIT0()     asm volatile("cp.async.wait_group 0;" ::: "memory")

__device__ __forceinline__ void ldmx4(uint32_t* f, uint32_t addr) {
    asm volatile("ldmatrix.sync.aligned.m8n8.x4.shared.b16 {%0,%1,%2,%3}, [%4];"
        : "=r"(f[0]), "=r"(f[1]), "=r"(f[2]), "=r"(f[3]) : "r"(addr));
}
__device__ __forceinline__ void mma16816(float* d, const uint32_t* a, const uint32_t* b) {
    asm volatile("mma.sync.aligned.m16n8k16.row.col.f32.bf16.bf16.f32 "
        "{%0,%1,%2,%3}, {%4,%5,%6,%7}, {%8,%9}, {%0,%1,%2,%3};"
        : "+f"(d[0]), "+f"(d[1]), "+f"(d[2]), "+f"(d[3])
        : "r"(a[0]), "r"(a[1]), "r"(a[2]), "r"(a[3]), "r"(b[0]), "r"(b[1]));
}
__device__ __forceinline__ void st_hl(bf16* hi, bf16* lo, size_t off, float a, float b) {
    bf162 h = __floats2bfloat162_rn(a, b);
    float2 f = __bfloat1622float2(h);
    bf162 l = __floats2bfloat162_rn(a - f.x, b - f.y);
    *(bf162*)(hi + off) = h;
    *(bf162*)(lo + off) = l;
}
__device__ __forceinline__ void pack_hl(float x, float y, uint32_t& hp, uint32_t& lp) {
    bf162 h = __floats2bfloat162_rn(x, y);
    float2 f = __bfloat1622float2(h);
    bf162 l = __floats2bfloat162_rn(x - f.x, y - f.y);
    hp = *(uint32_t*)&h;
    lp = *(uint32_t*)&l;
}

// ---------------- bf16x3 tensor GEMM (verified core, UNTOUCHED) ----------------
extern __shared__ char dsm[];
__global__ void __launch_bounds__(128, 2) gemm_bf3(
    const bf16* __restrict__ Ahi, const bf16* __restrict__ Alo,
    const bf16* __restrict__ Bhi, const bf16* __restrict__ Blo,
    float* __restrict__ C, bf16* __restrict__ Chi, bf16* __restrict__ Clo,
    int lda, int ldb, int ldc, int K)
{
    int row0 = blockIdx.y * BM, col0 = blockIdx.x * BN;
    size_t aoff = (size_t)row0 * lda;
    size_t boff = (size_t)col0 * ldb;
    Ahi += aoff; Alo += aoff; Bhi += boff; Blo += boff;
    size_t coff = (size_t)row0 * ldc + col0;
    int nch = K / BK;

    uint32_t sb = smem_u32(dsm);
    int tid = threadIdx.x;
    int lane = tid & 31, wid = tid >> 5;
    int wm = wid >> 1, wn = wid & 1;

    uint32_t smo[4];
    size_t gA[4], gB[4];
#pragma unroll
    for (int i = 0; i < 4; i++) {
        int id = tid + i * 128;
        int r = id >> 2, c = id & 3;
        smo[i] = SWZ64((uint32_t)(r * 64 + c * 16));
        gA[i] = (size_t)r * lda + c * 8;
        gB[i] = (size_t)r * ldb + c * 8;
    }

    float acc[4][8][4];
#pragma unroll
    for (int i = 0; i < 4; i++)
#pragma unroll
        for (int j = 0; j < 8; j++)
#pragma unroll
            for (int e = 0; e < 4; e++) acc[i][j][e] = 0.f;

#define ISSUE(ch, s) do {                                                  \
        uint32_t st_ = sb + (uint32_t)(s) * 32768u;                        \
        int k0_ = (ch) * BK;                                               \
        _Pragma("unroll")                                                  \
        for (int i_ = 0; i_ < 4; i_++) {                                   \
            CP16(st_ + smo[i_],          Ahi + gA[i_] + k0_);              \
            CP16(st_ + 8192  + smo[i_],  Alo + gA[i_] + k0_);              \
            CP16(st_ + 16384 + smo[i_],  Bhi + gB[i_] + k0_);              \
            CP16(st_ + 24576 + smo[i_],  Blo + gB[i_] + k0_);              \
        }                                                                  \
        CP_COMMIT();                                                       \
    } while (0)

    ISSUE(0, 0);
    if (nch > 1) ISSUE(1, 1);

    int a_r = lane & 15;
    int a_c = lane >> 4;
    int b_q = lane >> 3;
    int b_r = (b_q >> 1) * 8 + (lane & 7);
    int b_c = b_q & 1;

    for (int ch = 0; ch < nch; ch++) {
        if (ch + 1 < nch) CP_WAIT1(); else CP_WAIT0();
        __syncthreads();
        if (ch + 2 < nch) ISSUE(ch + 2, (ch + 2) % 3);

        uint32_t st = sb + (uint32_t)(ch % 3) * 32768u;
#pragma unroll
        for (int ks = 0; ks < 2; ks++) {
            uint32_t ah[4][4], al[4][4];
#pragma unroll
            for (int mf = 0; mf < 4; mf++) {
                int row = wm * 64 + mf * 16 + a_r;
                uint32_t off = SWZ64((uint32_t)(row * 64 + (ks * 2 + a_c) * 16));
                ldmx4(ah[mf], st + off);
                ldmx4(al[mf], st + 8192 + off);
            }
#pragma unroll
            for (int np = 0; np < 4; np++) {
                int row = wn * 64 + np * 16 + b_r;
                uint32_t off = SWZ64((uint32_t)(row * 64 + (ks * 2 + b_c) * 16));
                uint32_t bh4[4], bl4[4];
                ldmx4(bh4, st + 16384 + off);
                ldmx4(bl4, st + 24576 + off);
#pragma unroll
                for (int mf = 0; mf < 4; mf++) {
                    float* d0 = acc[mf][np * 2];
                    mma16816(d0, ah[mf], bh4);
                    mma16816(d0, ah[mf], bl4);
                    mma16816(d0, al[mf], bh4);
                    float* d1 = acc[mf][np * 2 + 1];
                    mma16816(d1, ah[mf], bh4 + 2);
                    mma16816(d1, ah[mf], bl4 + 2);
                    mma16816(d1, al[mf], bh4 + 2);
                }
            }
        }
        __syncthreads();
    }

    int g = lane >> 2, tg = lane & 3;
#pragma unroll
    for (int mf = 0; mf < 4; mf++)
#pragma unroll
        for (int nf = 0; nf < 8; nf++) {
            int rA = wm * 64 + mf * 16 + g;
            int cc = wn * 64 + nf * 8 + tg * 2;
            float* d = acc[mf][nf];
            if (C) {
                *(float2*)(C + coff + (size_t)rA * ldc + cc)       = make_float2(d[0], d[1]);
                *(float2*)(C + coff + (size_t)(rA + 8) * ldc + cc) = make_float2(d[2], d[3]);
            } else {
                st_hl(Chi, Clo, coff + (size_t)rA * ldc + cc,       d[0], d[1]);
                st_hl(Chi, Clo, coff + (size_t)(rA + 8) * ldc + cc, d[2], d[3]);
            }
        }
#undef ISSUE
}

// ---------------- fused flash attention v3: 512 threads, column-split warps -----
// |s_scaled| <= sqrt(128) ~ 11.32; fixed max M=13; row factor cancels in p/l.
// 16 warps: wm = wid>>1 (16-row group), wn = wid&1 (32-col half of Bc=64).
// Each warp accumulates a PARTIAL o over its k-half; merged via smem at the end.
#define SMAX 13.0f
__global__ void __launch_bounds__(512, 1) flash_kernel(
    const bf16* __restrict__ Qhi, const bf16* __restrict__ Qlo,
    const bf16* __restrict__ Khi, const bf16* __restrict__ Klo,
    const bf16* __restrict__ Vthi, const bf16* __restrict__ Vtlo,
    bf16* __restrict__ ctxh, bf16* __restrict__ ctxl)
{
    int qt = (int)gridDim.x - 1 - (int)blockIdx.x;   // big tiles first
    int h = blockIdx.y;
    int kv = h >> 2;
    int tid = threadIdx.x, lane = tid & 31, wid = tid >> 5;
    int wm = wid >> 1, wn = wid & 1;

    uint32_t sb = smem_u32(dsm);
    const uint32_t ST0 = 65536;

    {
        size_t qg = (size_t)(qt * 128) * QDIM + (size_t)h * HD;
#pragma unroll
        for (int i = 0; i < 8; i++) {
            int id = tid + i * 512;
            int hl = id >> 11, rem = id & 2047;
            int row = rem >> 4, c = rem & 15;
            int kc = c >> 2, cc = c & 3;
            uint32_t dst = sb + (uint32_t)(hl * 32768 + kc * 8192) +
                           SWZ64((uint32_t)(row * 64 + cc * 16));
            const bf16* src = (hl ? Qlo : Qhi) + qg + (size_t)row * QDIM + kc * 32 + cc * 8;
            CP16(dst, src);
        }
        CP_COMMIT();
    }

#define KV_ISSUE(n, s) do {                                                     \
        uint32_t st_ = sb + ST0 + (uint32_t)(s) * 65536u;                       \
        int t0_ = (n) * 64;                                                     \
        _Pragma("unroll")                                                       \
        for (int i_ = 0; i_ < 4; i_++) {                                        \
            int id = tid + i_ * 512;                                            \
            int hl = id >> 10, rem = id & 1023;                                 \
            int row = rem >> 4, c = rem & 15;                                   \
            int kc = c >> 2, cc = c & 3;                                        \
            uint32_t dst = st_ + (uint32_t)(hl * 16384 + kc * 4096) +           \
                           SWZ64((uint32_t)(row * 64 + cc * 16));               \
            const bf16* src = (hl ? Klo : Khi) +                                \
                ((size_t)kv * SEQ + t0_ + row) * HD + kc * 32 + cc * 8;         \
            CP16(dst, src);                                                     \
        }                                                                       \
        _Pragma("unroll")                                                       \
        for (int i_ = 0; i_ < 4; i_++) {                                        \
            int id = tid + i_ * 512;                                            \
            int hl = id >> 10, rem = id & 1023;                                 \
            int row = rem >> 3, c = rem & 7;                                    \
            int tc = c >> 2, cc = c & 3;                                        \
            uint32_t dst = st_ + 32768u + (uint32_t)(hl * 16384 + tc * 8192) +  \
                           SWZ64((uint32_t)(row * 64 + cc * 16));               \
            const bf16* src = (hl ? Vtlo : Vthi) +                              \
                ((size_t)kv * HD + row) * SEQ + t0_ + tc * 32 + cc * 8;         \
            CP16(dst, src);                                                     \
        }                                                                       \
        CP_COMMIT();                                                            \
    } while (0)

    int nsteps = 2 * qt + 2;
    KV_ISSUE(0, 0);
    if (nsteps > 1) KV_ISSUE(1, 1);

    float o[16][4];
#pragma unroll
    for (int i = 0; i < 16; i++)
#pragma unroll
        for (int e = 0; e < 4; e++) o[i][e] = 0.f;
    float l0 = 0.f, l1 = 0.f;

    int a_r = lane & 15, a_c = lane >> 4;
    int b_q = lane >> 3, b_r = (b_q >> 1) * 8 + (lane & 7), b_c = b_q & 1;

    for (int n = 0; n < nsteps; n++) {
        if (n + 1 < nsteps) CP_WAIT1(); else CP_WAIT0();
        __syncthreads();
        uint32_t st = sb + ST0 + (uint32_t)(n & 1) * 65536u;

        float s[4][4];
#pragma unroll
        for (int i = 0; i < 4; i++)
#pragma unroll
            for (int e = 0; e < 4; e++) s[i][e] = 0.f;

#pragma unroll
        for (int kc = 0; kc < 4; kc++)
#pragma unroll
            for (int ks = 0; ks < 2; ks++) {
                uint32_t ah[4], al[4];
                {
                    int row = wm * 16 + a_r;
                    uint32_t off = (uint32_t)(kc * 8192) +
                                   SWZ64((uint32_t)(row * 64 + (ks * 2 + a_c) * 16));
                    ldmx4(ah, sb + off);
                    ldmx4(al, sb + 32768u + off);
                }
#pragma unroll
                for (int np = 0; np < 2; np++) {
                    int row = wn * 32 + np * 16 + b_r;
                    uint32_t off = (uint32_t)(kc * 4096) +
                                   SWZ64((uint32_t)(row * 64 + (ks * 2 + b_c) * 16));
                    uint32_t bh4[4], bl4[4];
                    ldmx4(bh4, st + off);
                    ldmx4(bl4, st + 16384u + off);
                    float* d0 = s[np * 2];
                    float* d1 = s[np * 2 + 1];
                    mma16816(d0, ah, bh4);
                    mma16816(d1, ah, bh4 + 2);
                    mma16816(d0, ah, bl4);
                    mma16816(d1, ah, bl4 + 2);
                    mma16816(d0, al, bh4);
                    mma16816(d1, al, bh4 + 2);
                }
            }

        if (n >= nsteps - 2) {
            int row0 = qt * 128 + wm * 16 + (lane >> 2);
            int colb = n * 64 + wn * 32 + (lane & 3) * 2;
#pragma unroll
            for (int nf = 0; nf < 4; nf++) {
                int c0 = colb + nf * 8;
                if (c0 > row0)         s[nf][0] = -1e30f;
                if (c0 + 1 > row0)     s[nf][1] = -1e30f;
                if (c0 > row0 + 8)     s[nf][2] = -1e30f;
                if (c0 + 1 > row0 + 8) s[nf][3] = -1e30f;
            }
        }

        // ---- static-max softmax (partial over this warp's 32 cols) ----
#pragma unroll
        for (int nf = 0; nf < 4; nf++) {
            s[nf][0] = __expf(s[nf][0] - SMAX);
            s[nf][1] = __expf(s[nf][1] - SMAX);
            s[nf][2] = __expf(s[nf][2] - SMAX);
            s[nf][3] = __expf(s[nf][3] - SMAX);
            l0 += s[nf][0] + s[nf][1];
            l1 += s[nf][2] + s[nf][3];
        }

        // ---- O += P V over this warp's 32-k slice ----
#pragma unroll
        for (int kb = 0; kb < 2; kb++) {
            uint32_t ph[4], pl[4];
            pack_hl(s[2 * kb][0],     s[2 * kb][1],     ph[0], pl[0]);
            pack_hl(s[2 * kb][2],     s[2 * kb][3],     ph[1], pl[1]);
            pack_hl(s[2 * kb + 1][0], s[2 * kb + 1][1], ph[2], pl[2]);
            pack_hl(s[2 * kb + 1][2], s[2 * kb + 1][3], ph[3], pl[3]);
            int gkb = wn * 2 + kb;
            uint32_t vbase = 32768u + (uint32_t)((gkb >> 1) * 8192);
            int kcol = ((gkb & 1) * 2 + b_c) * 16;
#pragma unroll
            for (int nb = 0; nb < 8; nb++) {
                int row = nb * 16 + b_r;
                uint32_t off = vbase + SWZ64((uint32_t)(row * 64 + kcol));
                uint32_t vh4[4], vl4[4];
                ldmx4(vh4, st + off);
                ldmx4(vl4, st + 16384u + off);
                float* d0 = o[nb * 2];
                float* d1 = o[nb * 2 + 1];
                mma16816(d0, ph, vh4);
                mma16816(d1, ph, vh4 + 2);
                mma16816(d0, pl, vh4);
                mma16816(d1, pl, vh4 + 2);
                mma16816(d0, ph, vl4);
                mma16816(d1, ph, vl4 + 2);
            }
        }
        __syncthreads();
        if (n + 2 < nsteps) KV_ISSUE(n + 2, n & 1);
    }

    // ---- quad-reduce own l (rows g, g+8 over this warp's 32 cols) ----
    l0 += __shfl_xor_sync(0xffffffffu, l0, 1);
    l0 += __shfl_xor_sync(0xffffffffu, l0, 2);
    l1 += __shfl_xor_sync(0xffffffffu, l1, 1);
    l1 += __shfl_xor_sync(0xffffffffu, l1, 2);

    // ---- cross-warp (wn) merge via stage smem (free after last step) ----
    float* red  = (float*)(dsm + 65536);           // 8 x 8KB
    float* lred = (float*)(dsm + 65536 + 65536);   // 256 floats
    if (wn == 1) {
        float* dst = red + wm * 2048 + lane * 4;
#pragma unroll
        for (int nf = 0; nf < 16; nf++)
            *(float4*)(dst + nf * 128) = make_float4(o[nf][0], o[nf][1], o[nf][2], o[nf][3]);
        if ((lane & 3) == 0) {
            int g = lane >> 2;
            lred[wm * 16 + g]     = l0;
            lred[wm * 16 + g + 8] = l1;
        }
    }
    __syncthreads();
    if (wn == 0) {
        float* srcp = red + wm * 2048 + lane * 4;
#pragma unroll
        for (int nf = 0; nf < 16; nf++) {
            float4 v = *(float4*)(srcp + nf * 128);
            o[nf][0] += v.x; o[nf][1] += v.y; o[nf][2] += v.z; o[nf][3] += v.w;
        }
        int g = lane >> 2;
        l0 += lred[wm * 16 + g];
        l1 += lred[wm * 16 + g + 8];

        float inv0 = 1.f / l0, inv1 = 1.f / l1;
        int row0 = qt * 128 + wm * 16 + g;
        size_t base = (size_t)row0 * QDIM + (size_t)h * HD;
#pragma unroll
        for (int nf = 0; nf < 16; nf++) {
            int col = nf * 8 + (lane & 3) * 2;
            st_hl(ctxh, ctxl, base + col,            o[nf][0] * inv0, o[nf][1] * inv0);
            st_hl(ctxh, ctxl, base + 8 * QDIM + col, o[nf][2] * inv1, o[nf][3] * inv1);
        }
    }
#undef KV_ISSUE
}

// ---------------- unified converter: weights (transpose) + x (elementwise) -----
__global__ void __launch_bounds__(256) convert_all(
    const float* __restrict__ x,
    const float* __restrict__ Wq, const float* __restrict__ Wk,
    const float* __restrict__ Wv, const float* __restrict__ Wo,
    bf16* __restrict__ xhi, bf16* __restrict__ xlo,
    bf16* __restrict__ Wqkvh, bf16* __restrict__ Wqkvl,
    bf16* __restrict__ Woh, bf16* __restrict__ Wol)
{
    __shared__ bf16 th[64][72];
    __shared__ bf16 tl[64][72];
    int t = blockIdx.x;
    int tid = threadIdx.x;

    if (t >= 5120) {
        size_t base4 = (size_t)(t - 5120) * 1024;
#pragma unroll
        for (int i = 0; i < 4; i++) {
            size_t idx = base4 + tid + i * 256;
            float4 v = ((const float4*)x)[idx];
            bf162 h01 = __floats2bfloat162_rn(v.x, v.y);
            bf162 h23 = __floats2bfloat162_rn(v.z, v.w);
            float2 f01 = __bfloat1622float2(h01);
            float2 f23 = __bfloat1622float2(h23);
            ((bf162*)xhi)[2 * idx]     = h01;
            ((bf162*)xhi)[2 * idx + 1] = h23;
            ((bf162*)xlo)[2 * idx]     = __floats2bfloat162_rn(v.x - f01.x, v.y - f01.y);
            ((bf162*)xlo)[2 * idx + 1] = __floats2bfloat162_rn(v.z - f23.x, v.w - f23.y);
        }
        return;
    }

    const float* W;
    bf16 *hi, *lo;
    int Kd, Nd, idx;
    if (t < 2048)      { W = Wq; hi = Wqkvh;                        lo = Wqkvl;                        Kd = DIN;  Nd = QDIM;  idx = t; }
    else if (t < 2560) { W = Wk; hi = Wqkvh + (size_t)QDIM * DIN;   lo = Wqkvl + (size_t)QDIM * DIN;   Kd = DIN;  Nd = KVDIM; idx = t - 2048; }
    else if (t < 3072) { W = Wv; hi = Wqkvh + (size_t)(QDIM + KVDIM) * DIN; lo = Wqkvl + (size_t)(QDIM + KVDIM) * DIN; Kd = DIN; Nd = KVDIM; idx = t - 2560; }
    else               { W = Wo; hi = Woh;                          lo = Wol;                          Kd = QDIM; Nd = DIN;   idx = t - 3072; }
    int ntn = Nd >> 6;
    int n0 = (idx % ntn) * 64, k0 = (idx / ntn) * 64;
#pragma unroll
    for (int i = 0; i < 4; i++) {
        int id = tid + i * 256;
        int r = id >> 4, c = (id & 15) * 4;
        float4 v = *(const float4*)(W + (size_t)(k0 + r) * Nd + n0 + c);
        float a[4] = {v.x, v.y, v.z, v.w};
#pragma unroll
        for (int j = 0; j < 4; j++) {
            bf16 h = __float2bfloat16_rn(a[j]);
            th[c + j][r] = h;
            tl[c + j][r] = __float2bfloat16_rn(a[j] - __bfloat162float(h));
        }
    }
    __syncthreads();
#pragma unroll
    for (int i = 0; i < 2; i++) {
        int id = tid + i * 256;
        int n = id >> 3, kb = (id & 7) * 8;
        uint4 vh = *(uint4*)&th[n][kb];
        uint4 vl = *(uint4*)&tl[n][kb];
        *(uint4*)(hi + (size_t)(n0 + n) * Kd + k0 + kb) = vh;
        *(uint4*)(lo + (size_t)(n0 + n) * Kd + k0 + kb) = vl;
    }
}

// ---------------- merged RMSNorm+RoPE (Q,K) + V transpose ----------------
__global__ void __launch_bounds__(256) norm_rope_qkv(
    const float* __restrict__ QKVp, float* __restrict__ Kout, float* __restrict__ Vout,
    bf16* __restrict__ Qhi, bf16* __restrict__ Qlo,
    bf16* __restrict__ Khi, bf16* __restrict__ Klo,
    bf16* __restrict__ Vthi, bf16* __restrict__ Vtlo,
    const float* __restrict__ q_scale, const float* __restrict__ k_scale,
    const float* __restrict__ cosb, const float* __restrict__ sinb, float scl)
{
    int tid = threadIdx.x;
    int hh = blockIdx.y;

    if (hh >= NH + NKV) {
        __shared__ float tile[32][33];
        int kv = hh - (NH + NKV);
        int bx = blockIdx.x;
        int t0 = (bx & 63) * 32, d0 = (bx >> 6) * 32;
        int tx = tid & 31, ty = tid >> 5;
        const float* Vp = QKVp + QDIM + KVDIM;
#pragma unroll
        for (int j = 0; j < 32; j += 8) {
            int t = t0 + ty + j;
            float v = Vp[(size_t)t * QKV + kv * HD + d0 + tx];
            tile[ty + j][tx] = v;
            Vout[((size_t)kv * SEQ + t) * HD + d0 + tx] = v;
        }
        __syncthreads();
#pragma unroll
        for (int j = 0; j < 32; j += 8) {
            int d = d0 + ty + j, t = t0 + tx;
            float v = tile[tx][ty + j];
            size_t off = ((size_t)kv * HD + d) * SEQ + t;
            bf16 h = __float2bfloat16_rn(v);
            Vthi[off] = h;
            Vtlo[off] = __float2bfloat16_rn(v - __bfloat162float(h));
        }
        return;
    }

    int wid = tid >> 5, lane = tid & 31;
    int t = blockIdx.x * 8 + wid;
    int d = lane * 2;

    const float* scale;
    const float* base;
    bf16 *outh, *outl;
    float* outf = nullptr;
    size_t ob;
    float premul;
    if (hh < NH) {
        scale = q_scale; premul = scl;
        base = QKVp + (size_t)t * QKV + (size_t)hh * HD;
        outh = Qhi; outl = Qlo;
        ob = (size_t)t * QDIM + (size_t)hh * HD;
    } else {
        int h = hh - NH;
        scale = k_scale; premul = 1.0f;
        base = QKVp + (size_t)t * QKV + QDIM + (size_t)h * HD;
        outh = Khi; outl = Klo;
        outf = Kout;
        ob = (size_t)t * HD + (size_t)h * SEQ * HD;
    }

    float2 a = *(const float2*)(base + d);
    float2 b = *(const float2*)(base + d + 64);
    float ssq = a.x * a.x + a.y * a.y + b.x * b.x + b.y * b.y;
#pragma unroll
    for (int s = 16; s > 0; s >>= 1) ssq += __shfl_xor_sync(0xffffffffu, ssq, s);
    float rms = rsqrtf(ssq * (1.0f / 128.0f) + 1e-6f);
    float2 n1 = *(const float2*)(scale + d);
    float2 n2 = *(const float2*)(scale + d + 64);
    float a0 = a.x * rms * n1.x, a1 = a.y * rms * n1.y;
    float b0 = b.x * rms * n2.x, b1 = b.y * rms * n2.y;
    size_t cb = (size_t)t * HD;
    float2 c1 = *(const float2*)(cosb + cb + d);
    float2 s1 = *(const float2*)(sinb + cb + d);
    float2 c2 = *(const float2*)(cosb + cb + d + 64);
    float2 s2 = *(const float2*)(sinb + cb + d + 64);
    float o10 = (a0 * c1.x - b0 * s1.x) * premul;
    float o11 = (a1 * c1.y - b1 * s1.y) * premul;
    float o20 = (b0 * c2.x + a0 * s2.x) * premul;
    float o21 = (b1 * c2.y + a1 * s2.y) * premul;
    st_hl(outh, outl, ob + d,      o10, o11);
    st_hl(outh, outl, ob + d + 64, o20, o21);
    if (outf) {
        *(float2*)(outf + ob + d)      = make_float2(o10, o11);
        *(float2*)(outf + ob + d + 64) = make_float2(o20, o21);
    }
}

// ---------------- launch ----------------
extern "C" void kernel_launch(void* const* d_in, const int* in_sizes, int n_in,
                              void* d_out, int out_size)
{
    const float* x       = (const float*)d_in[0];
    const float* Wq      = (const float*)d_in[1];
    const float* Wk      = (const float*)d_in[2];
    const float* Wv      = (const float*)d_in[3];
    const float* Wo      = (const float*)d_in[4];
    const float* q_scale = (const float*)d_in[5];
    const float* k_scale = (const float*)d_in[6];
    const float* cosb    = (const float*)d_in[7];
    const float* sinb    = (const float*)d_in[8];

    float* out  = (float*)d_out;
    float* Kout = out  + (size_t)SEQ * DIN;
    float* Vout = Kout + (size_t)NKV * SEQ * HD;

    bf16 *xhi, *xlo, *Wqkvh, *Wqkvl, *Woh, *Wol;
    bf16 *Qhi, *Qlo, *Khi, *Klo, *Vthi, *Vtlo, *ctxh, *ctxl;
    float* QKVp;
    cudaGetSymbolAddress((void**)&xhi, g_xhi);     cudaGetSymbolAddress((void**)&xlo, g_xlo);
    cudaGetSymbolAddress((void**)&Wqkvh, g_Wqkvh); cudaGetSymbolAddress((void**)&Wqkvl, g_Wqkvl);
    cudaGetSymbolAddress((void**)&Woh, g_Woh);     cudaGetSymbolAddress((void**)&Wol, g_Wol);
    cudaGetSymbolAddress((void**)&QKVp, g_QKVp);
    cudaGetSymbolAddress((void**)&Qhi, g_Qhi);     cudaGetSymbolAddress((void**)&Qlo, g_Qlo);
    cudaGetSymbolAddress((void**)&Khi, g_Khi);     cudaGetSymbolAddress((void**)&Klo, g_Klo);
    cudaGetSymbolAddress((void**)&Vthi, g_Vthi);   cudaGetSymbolAddress((void**)&Vtlo, g_Vtlo);
    cudaGetSymbolAddress((void**)&ctxh, g_ctxh);   cudaGetSymbolAddress((void**)&ctxl, g_ctxl);

    const int SMEM = 3 * 32768;           // gemm: 98304
    const int FSMEM = 65536 + 2 * 65536;  // flash: 196608
    cudaFuncSetAttribute(gemm_bf3, cudaFuncAttributeMaxDynamicSharedMemorySize, SMEM);
    cudaFuncSetAttribute(flash_kernel, cudaFuncAttributeMaxDynamicSharedMemorySize, FSMEM);

    dim3 blk(128);
    const float scl = 0.08838834764831845f;   // 1/sqrt(128)

    // launch 1: all input conversions
    convert_all<<<6144, 256>>>(x, Wq, Wk, Wv, Wo, xhi, xlo, Wqkvh, Wqkvl, Woh, Wol);

    // launch 2: merged QKV projection -> QKVp fp32 [2048][6144]
    gemm_bf3<<<dim3(QKV / BN, SEQ / BM), blk, SMEM>>>(
        xhi, xlo, Wqkvh, Wqkvl, QKVp, nullptr, nullptr, DIN, DIN, QKV, DIN);

    // launch 3: norm/rope (Q,K) + V transpose
    norm_rope_qkv<<<dim3(SEQ / 8, NH + 2 * NKV), 256>>>(
        QKVp, Kout, Vout, Qhi, Qlo, Khi, Klo, Vthi, Vtlo,
        q_scale, k_scale, cosb, sinb, scl);

    // launch 4: fused attention (512 threads) -> ctx hi/lo
    flash_kernel<<<dim3(16, NH), 512, FSMEM>>>(Qhi, Qlo, Khi, Klo, Vthi, Vtlo, ctxh, ctxl);

    // launch 5: output projection -> out fp32
    gemm_bf3<<<dim3(DIN / BN, SEQ / BM), blk, SMEM>>>(
        ctxh, ctxl, Woh, Wol, out, nullptr, nullptr, QDIM, QDIM, DIN, QDIM);
}

// round 16
// speedup vs baseline: 1.0205x; 1.0205x over previous
#include <cuda_runtime.h>
#include <cuda_bf16.h>
#include <cstdint>

#define SEQ 2048
#define DIN 2048
#define NH 32
#define NKV 8
#define HD 128
#define QDIM 4096
#define KVDIM 1024
#define QKV (QDIM + 2 * KVDIM)   // 6144

typedef __nv_bfloat16 bf16;
typedef __nv_bfloat162 bf162;

#define BM 128
#define BN 128
#define BK 32

// ---------------- static scratch (no allocs allowed) ----------------
__device__ bf16 g_xhi[(size_t)SEQ * DIN];
__device__ bf16 g_xlo[(size_t)SEQ * DIN];
__device__ bf16 g_Wqkvh[(size_t)QKV * DIN], g_Wqkvl[(size_t)QKV * DIN];
__device__ bf16 g_Woh[(size_t)DIN * QDIM],  g_Wol[(size_t)DIN * QDIM];
__device__ float g_QKVp[(size_t)SEQ * QKV];
__device__ bf16 g_Qhi[(size_t)SEQ * QDIM], g_Qlo[(size_t)SEQ * QDIM];
__device__ bf16 g_Khi[(size_t)NKV * SEQ * HD], g_Klo[(size_t)NKV * SEQ * HD];
__device__ bf16 g_Vthi[(size_t)NKV * HD * SEQ], g_Vtlo[(size_t)NKV * HD * SEQ];
__device__ bf16 g_ctxh[(size_t)SEQ * QDIM], g_ctxl[(size_t)SEQ * QDIM];

// ---------------- helpers ----------------
__device__ __forceinline__ uint32_t smem_u32(const void* p) {
    uint32_t a;
    asm("{ .reg .u64 t; cvta.to.shared.u64 t, %1; cvt.u32.u64 %0, t; }" : "=r"(a) : "l"(p));
    return a;
}
#define SWZ64(o) ((o) ^ ((((o) >> 7) & 3u) << 4))

#define CP16(dst, src) asm volatile("cp.async.cg.shared.global [%0], [%1], 16;" :: "r"(dst), "l"(src))
#define CP_COMMIT()    asm volatile("cp.async.commit_group;" ::: "memory")
#define CP_WAIT1()     asm volatile("cp.async.wait_group 1;" ::: "memory")
#define CP_WAIT0()     asm volatile("cp.async.wait_group 0;" ::: "memory")

__device__ __forceinline__ void ldmx4(uint32_t* f, uint32_t addr) {
    asm volatile("ldmatrix.sync.aligned.m8n8.x4.shared.b16 {%0,%1,%2,%3}, [%4];"
        : "=r"(f[0]), "=r"(f[1]), "=r"(f[2]), "=r"(f[3]) : "r"(addr));
}
__device__ __forceinline__ void mma16816(float* d, const uint32_t* a, const uint32_t* b) {
    asm volatile("mma.sync.aligned.m16n8k16.row.col.f32.bf16.bf16.f32 "
        "{%0,%1,%2,%3}, {%4,%5,%6,%7}, {%8,%9}, {%0,%1,%2,%3};"
        : "+f"(d[0]), "+f"(d[1]), "+f"(d[2]), "+f"(d[3])
        : "r"(a[0]), "r"(a[1]), "r"(a[2]), "r"(a[3]), "r"(b[0]), "r"(b[1]));
}
__device__ __forceinline__ void st_hl(bf16* hi, bf16* lo, size_t off, float a, float b) {
    bf162 h = __floats2bfloat162_rn(a, b);
    float2 f = __bfloat1622float2(h);
    bf162 l = __floats2bfloat162_rn(a - f.x, b - f.y);
    *(bf162*)(hi + off) = h;
    *(bf162*)(lo + off) = l;
}
__device__ __forceinline__ void pack_hl(float x, float y, uint32_t& hp, uint32_t& lp) {
    bf162 h = __floats2bfloat162_rn(x, y);
    float2 f = __bfloat1622float2(h);
    bf162 l = __floats2bfloat162_rn(x - f.x, y - f.y);
    hp = *(uint32_t*)&h;
    lp = *(uint32_t*)&l;
}

// ---------------- bf16x3 tensor GEMM (verified core) ----------------
extern __shared__ char dsm[];
__global__ void __launch_bounds__(128, 2) gemm_bf3(
    const bf16* __restrict__ Ahi, const bf16* __restrict__ Alo,
    const bf16* __restrict__ Bhi, const bf16* __restrict__ Blo,
    float* __restrict__ C, bf16* __restrict__ Chi, bf16* __restrict__ Clo,
    int lda, int ldb, int ldc, int K)
{
    int row0 = blockIdx.y * BM, col0 = blockIdx.x * BN;
    size_t aoff = (size_t)row0 * lda;
    size_t boff = (size_t)col0 * ldb;
    Ahi += aoff; Alo += aoff; Bhi += boff; Blo += boff;
    size_t coff = (size_t)row0 * ldc + col0;
    int nch = K / BK;

    uint32_t sb = smem_u32(dsm);
    int tid = threadIdx.x;
    int lane = tid & 31, wid = tid >> 5;
    int wm = wid >> 1, wn = wid & 1;

    uint32_t smo[4];
    size_t gA[4], gB[4];
#pragma unroll
    for (int i = 0; i < 4; i++) {
        int id = tid + i * 128;
        int r = id >> 2, c = id & 3;
        smo[i] = SWZ64((uint32_t)(r * 64 + c * 16));
        gA[i] = (size_t)r * lda + c * 8;
        gB[i] = (size_t)r * ldb + c * 8;
    }

    float acc[4][8][4];
#pragma unroll
    for (int i = 0; i < 4; i++)
#pragma unroll
        for (int j = 0; j < 8; j++)
#pragma unroll
            for (int e = 0; e < 4; e++) acc[i][j][e] = 0.f;

#define ISSUE(ch, s) do {                                                  \
        uint32_t st_ = sb + (uint32_t)(s) * 32768u;                        \
        int k0_ = (ch) * BK;                                               \
        _Pragma("unroll")                                                  \
        for (int i_ = 0; i_ < 4; i_++) {                                   \
            CP16(st_ + smo[i_],          Ahi + gA[i_] + k0_);              \
            CP16(st_ + 8192  + smo[i_],  Alo + gA[i_] + k0_);              \
            CP16(st_ + 16384 + smo[i_],  Bhi + gB[i_] + k0_);              \
            CP16(st_ + 24576 + smo[i_],  Blo + gB[i_] + k0_);              \
        }                                                                  \
        CP_COMMIT();                                                       \
    } while (0)

    ISSUE(0, 0);
    if (nch > 1) ISSUE(1, 1);

    int a_r = lane & 15;
    int a_c = lane >> 4;
    int b_q = lane >> 3;
    int b_r = (b_q >> 1) * 8 + (lane & 7);
    int b_c = b_q & 1;

    for (int ch = 0; ch < nch; ch++) {
        if (ch + 1 < nch) CP_WAIT1(); else CP_WAIT0();
        __syncthreads();
        if (ch + 2 < nch) ISSUE(ch + 2, (ch + 2) % 3);

        uint32_t st = sb + (uint32_t)(ch % 3) * 32768u;
#pragma unroll
        for (int ks = 0; ks < 2; ks++) {
            uint32_t ah[4][4], al[4][4];
#pragma unroll
            for (int mf = 0; mf < 4; mf++) {
                int row = wm * 64 + mf * 16 + a_r;
                uint32_t off = SWZ64((uint32_t)(row * 64 + (ks * 2 + a_c) * 16));
                ldmx4(ah[mf], st + off);
                ldmx4(al[mf], st + 8192 + off);
            }
#pragma unroll
            for (int np = 0; np < 4; np++) {
                int row = wn * 64 + np * 16 + b_r;
                uint32_t off = SWZ64((uint32_t)(row * 64 + (ks * 2 + b_c) * 16));
                uint32_t bh4[4], bl4[4];
                ldmx4(bh4, st + 16384 + off);
                ldmx4(bl4, st + 24576 + off);
#pragma unroll
                for (int mf = 0; mf < 4; mf++) {
                    float* d0 = acc[mf][np * 2];
                    mma16816(d0, ah[mf], bh4);
                    mma16816(d0, ah[mf], bl4);
                    mma16816(d0, al[mf], bh4);
                    float* d1 = acc[mf][np * 2 + 1];
                    mma16816(d1, ah[mf], bh4 + 2);
                    mma16816(d1, ah[mf], bl4 + 2);
                    mma16816(d1, al[mf], bh4 + 2);
                }
            }
        }
        __syncthreads();
    }

    int g = lane >> 2, tg = lane & 3;
#pragma unroll
    for (int mf = 0; mf < 4; mf++)
#pragma unroll
        for (int nf = 0; nf < 8; nf++) {
            int rA = wm * 64 + mf * 16 + g;
            int cc = wn * 64 + nf * 8 + tg * 2;
            float* d = acc[mf][nf];
            if (C) {
                *(float2*)(C + coff + (size_t)rA * ldc + cc)       = make_float2(d[0], d[1]);
                *(float2*)(C + coff + (size_t)(rA + 8) * ldc + cc) = make_float2(d[2], d[3]);
            } else {
                st_hl(Chi, Clo, coff + (size_t)rA * ldc + cc,       d[0], d[1]);
                st_hl(Chi, Clo, coff + (size_t)(rA + 8) * ldc + cc, d[2], d[3]);
            }
        }
#undef ISSUE
}

// ---------------- fused flash attention (static-max + d0/d1 interleave) ----------
// |s_scaled| <= sqrt(128) ~ 11.32; fixed max M=13; row factor cancels in p/l.
#define SMAX 13.0f
__global__ void __launch_bounds__(256, 1) flash_kernel(
    const bf16* __restrict__ Qhi, const bf16* __restrict__ Qlo,
    const bf16* __restrict__ Khi, const bf16* __restrict__ Klo,
    const bf16* __restrict__ Vthi, const bf16* __restrict__ Vtlo,
    bf16* __restrict__ ctxh, bf16* __restrict__ ctxl)
{
    int qt = (int)gridDim.x - 1 - (int)blockIdx.x;   // big tiles first
    int h = blockIdx.y;
    int kv = h >> 2;
    int tid = threadIdx.x, lane = tid & 31, wid = tid >> 5;

    uint32_t sb = smem_u32(dsm);
    const uint32_t ST0 = 65536;

    {
        size_t qg = (size_t)(qt * 128) * QDIM + (size_t)h * HD;
#pragma unroll
        for (int i = 0; i < 16; i++) {
            int id = tid + i * 256;
            int hl = id >> 11, rem = id & 2047;
            int row = rem >> 4, c = rem & 15;
            int kc = c >> 2, cc = c & 3;
            uint32_t dst = sb + (uint32_t)(hl * 32768 + kc * 8192) +
                           SWZ64((uint32_t)(row * 64 + cc * 16));
            const bf16* src = (hl ? Qlo : Qhi) + qg + (size_t)row * QDIM + kc * 32 + cc * 8;
            CP16(dst, src);
        }
        CP_COMMIT();
    }

#define KV_ISSUE(n, s) do {                                                     \
        uint32_t st_ = sb + ST0 + (uint32_t)(s) * 65536u;                       \
        int t0_ = (n) * 64;                                                     \
        _Pragma("unroll")                                                       \
        for (int i_ = 0; i_ < 8; i_++) {                                        \
            int id = tid + i_ * 256;                                            \
            int hl = id >> 10, rem = id & 1023;                                 \
            int row = rem >> 4, c = rem & 15;                                   \
            int kc = c >> 2, cc = c & 3;                                        \
            uint32_t dst = st_ + (uint32_t)(hl * 16384 + kc * 4096) +           \
                           SWZ64((uint32_t)(row * 64 + cc * 16));               \
            const bf16* src = (hl ? Klo : Khi) +                                \
                ((size_t)kv * SEQ + t0_ + row) * HD + kc * 32 + cc * 8;         \
            CP16(dst, src);                                                     \
        }                                                                       \
        _Pragma("unroll")                                                       \
        for (int i_ = 0; i_ < 8; i_++) {                                        \
            int id = tid + i_ * 256;                                            \
            int hl = id >> 10, rem = id & 1023;                                 \
            int row = rem >> 3, c = rem & 7;                                    \
            int tc = c >> 2, cc = c & 3;                                        \
            uint32_t dst = st_ + 32768u + (uint32_t)(hl * 16384 + tc * 8192) +  \
                           SWZ64((uint32_t)(row * 64 + cc * 16));               \
            const bf16* src = (hl ? Vtlo : Vthi) +                              \
                ((size_t)kv * HD + row) * SEQ + t0_ + tc * 32 + cc * 8;         \
            CP16(dst, src);                                                     \
        }                                                                       \
        CP_COMMIT();                                                            \
    } while (0)

    int nsteps = 2 * qt + 2;
    KV_ISSUE(0, 0);
    if (nsteps > 1) KV_ISSUE(1, 1);

    float o[16][4];
#pragma unroll
    for (int i = 0; i < 16; i++)
#pragma unroll
        for (int e = 0; e < 4; e++) o[i][e] = 0.f;
    float l0 = 0.f, l1 = 0.f;

    int a_r = lane & 15, a_c = lane >> 4;
    int b_q = lane >> 3, b_r = (b_q >> 1) * 8 + (lane & 7), b_c = b_q & 1;

    for (int n = 0; n < nsteps; n++) {
        if (n + 1 < nsteps) CP_WAIT1(); else CP_WAIT0();
        __syncthreads();
        uint32_t st = sb + ST0 + (uint32_t)(n & 1) * 65536u;

        float s[8][4];
#pragma unroll
        for (int i = 0; i < 8; i++)
#pragma unroll
            for (int e = 0; e < 4; e++) s[i][e] = 0.f;

#pragma unroll
        for (int kc = 0; kc < 4; kc++)
#pragma unroll
            for (int ks = 0; ks < 2; ks++) {
                uint32_t ah[4], al[4];
                {
                    int row = wid * 16 + a_r;
                    uint32_t off = (uint32_t)(kc * 8192) +
                                   SWZ64((uint32_t)(row * 64 + (ks * 2 + a_c) * 16));
                    ldmx4(ah, sb + off);
                    ldmx4(al, sb + 32768u + off);
                }
#pragma unroll
                for (int np = 0; np < 4; np++) {
                    int row = np * 16 + b_r;
                    uint32_t off = (uint32_t)(kc * 4096) +
                                   SWZ64((uint32_t)(row * 64 + (ks * 2 + b_c) * 16));
                    uint32_t bh4[4], bl4[4];
                    ldmx4(bh4, st + off);
                    ldmx4(bl4, st + 16384u + off);
                    float* d0 = s[np * 2];
                    float* d1 = s[np * 2 + 1];
                    mma16816(d0, ah, bh4);
                    mma16816(d1, ah, bh4 + 2);
                    mma16816(d0, ah, bl4);
                    mma16816(d1, ah, bl4 + 2);
                    mma16816(d0, al, bh4);
                    mma16816(d1, al, bh4 + 2);
                }
            }

        if (n >= nsteps - 2) {
            int row0 = qt * 128 + wid * 16 + (lane >> 2);
            int colb = n * 64 + (lane & 3) * 2;
#pragma unroll
            for (int nf = 0; nf < 8; nf++) {
                int c0 = colb + nf * 8;
                if (c0 > row0)         s[nf][0] = -1e30f;
                if (c0 + 1 > row0)     s[nf][1] = -1e30f;
                if (c0 > row0 + 8)     s[nf][2] = -1e30f;
                if (c0 + 1 > row0 + 8) s[nf][3] = -1e30f;
            }
        }

        // ---- static-max softmax ----
#pragma unroll
        for (int nf = 0; nf < 8; nf++) {
            s[nf][0] = __expf(s[nf][0] - SMAX);
            s[nf][1] = __expf(s[nf][1] - SMAX);
            s[nf][2] = __expf(s[nf][2] - SMAX);
            s[nf][3] = __expf(s[nf][3] - SMAX);
            l0 += s[nf][0] + s[nf][1];
            l1 += s[nf][2] + s[nf][3];
        }

        // ---- O += P V (bf16x3), interleaved d0/d1 ----
#pragma unroll
        for (int kb = 0; kb < 4; kb++) {
            uint32_t ph[4], pl[4];
            pack_hl(s[2 * kb][0],     s[2 * kb][1],     ph[0], pl[0]);
            pack_hl(s[2 * kb][2],     s[2 * kb][3],     ph[1], pl[1]);
            pack_hl(s[2 * kb + 1][0], s[2 * kb + 1][1], ph[2], pl[2]);
            pack_hl(s[2 * kb + 1][2], s[2 * kb + 1][3], ph[3], pl[3]);
            uint32_t vbase = 32768u + (uint32_t)((kb >> 1) * 8192);
            int kcol = ((kb & 1) * 2 + b_c) * 16;
#pragma unroll
            for (int nb = 0; nb < 8; nb++) {
                int row = nb * 16 + b_r;
                uint32_t off = vbase + SWZ64((uint32_t)(row * 64 + kcol));
                uint32_t vh4[4], vl4[4];
                ldmx4(vh4, st + off);
                ldmx4(vl4, st + 16384u + off);
                float* d0 = o[nb * 2];
                float* d1 = o[nb * 2 + 1];
                mma16816(d0, ph, vh4);
                mma16816(d1, ph, vh4 + 2);
                mma16816(d0, pl, vh4);
                mma16816(d1, pl, vh4 + 2);
                mma16816(d0, ph, vl4);
                mma16816(d1, ph, vl4 + 2);
            }
        }
        __syncthreads();
        if (n + 2 < nsteps) KV_ISSUE(n + 2, n & 1);
    }

    l0 += __shfl_xor_sync(0xffffffffu, l0, 1);
    l0 += __shfl_xor_sync(0xffffffffu, l0, 2);
    l1 += __shfl_xor_sync(0xffffffffu, l1, 1);
    l1 += __shfl_xor_sync(0xffffffffu, l1, 2);
    float inv0 = 1.f / l0, inv1 = 1.f / l1;
    int row0 = qt * 128 + wid * 16 + (lane >> 2);
    size_t base = (size_t)row0 * QDIM + (size_t)h * HD;
#pragma unroll
    for (int nf = 0; nf < 16; nf++) {
        int col = nf * 8 + (lane & 3) * 2;
        st_hl(ctxh, ctxl, base + col,             o[nf][0] * inv0, o[nf][1] * inv0);
        st_hl(ctxh, ctxl, base + 8 * QDIM + col,  o[nf][2] * inv1, o[nf][3] * inv1);
    }
#undef KV_ISSUE
}

// ---------------- unified converter: weights (transpose) + x (elementwise) -----
__global__ void __launch_bounds__(256) convert_all(
    const float* __restrict__ x,
    const float* __restrict__ Wq, const float* __restrict__ Wk,
    const float* __restrict__ Wv, const float* __restrict__ Wo,
    bf16* __restrict__ xhi, bf16* __restrict__ xlo,
    bf16* __restrict__ Wqkvh, bf16* __restrict__ Wqkvl,
    bf16* __restrict__ Woh, bf16* __restrict__ Wol)
{
    __shared__ bf16 th[64][72];
    __shared__ bf16 tl[64][72];
    int t = blockIdx.x;
    int tid = threadIdx.x;

    if (t >= 5120) {
        size_t base4 = (size_t)(t - 5120) * 1024;
#pragma unroll
        for (int i = 0; i < 4; i++) {
            size_t idx = base4 + tid + i * 256;
            float4 v = ((const float4*)x)[idx];
            bf162 h01 = __floats2bfloat162_rn(v.x, v.y);
            bf162 h23 = __floats2bfloat162_rn(v.z, v.w);
            float2 f01 = __bfloat1622float2(h01);
            float2 f23 = __bfloat1622float2(h23);
            ((bf162*)xhi)[2 * idx]     = h01;
            ((bf162*)xhi)[2 * idx + 1] = h23;
            ((bf162*)xlo)[2 * idx]     = __floats2bfloat162_rn(v.x - f01.x, v.y - f01.y);
            ((bf162*)xlo)[2 * idx + 1] = __floats2bfloat162_rn(v.z - f23.x, v.w - f23.y);
        }
        return;
    }

    const float* W;
    bf16 *hi, *lo;
    int Kd, Nd, idx;
    if (t < 2048)      { W = Wq; hi = Wqkvh;                        lo = Wqkvl;                        Kd = DIN;  Nd = QDIM;  idx = t; }
    else if (t < 2560) { W = Wk; hi = Wqkvh + (size_t)QDIM * DIN;   lo = Wqkvl + (size_t)QDIM * DIN;   Kd = DIN;  Nd = KVDIM; idx = t - 2048; }
    else if (t < 3072) { W = Wv; hi = Wqkvh + (size_t)(QDIM + KVDIM) * DIN; lo = Wqkvl + (size_t)(QDIM + KVDIM) * DIN; Kd = DIN; Nd = KVDIM; idx = t - 2560; }
    else               { W = Wo; hi = Woh;                          lo = Wol;                          Kd = QDIM; Nd = DIN;   idx = t - 3072; }
    int ntn = Nd >> 6;
    int n0 = (idx % ntn) * 64, k0 = (idx / ntn) * 64;
#pragma unroll
    for (int i = 0; i < 4; i++) {
        int id = tid + i * 256;
        int r = id >> 4, c = (id & 15) * 4;
        float4 v = *(const float4*)(W + (size_t)(k0 + r) * Nd + n0 + c);
        float a[4] = {v.x, v.y, v.z, v.w};
#pragma unroll
        for (int j = 0; j < 4; j++) {
            bf16 h = __float2bfloat16_rn(a[j]);
            th[c + j][r] = h;
            tl[c + j][r] = __float2bfloat16_rn(a[j] - __bfloat162float(h));
        }
    }
    __syncthreads();
#pragma unroll
    for (int i = 0; i < 2; i++) {
        int id = tid + i * 256;
        int n = id >> 3, kb = (id & 7) * 8;
        uint4 vh = *(uint4*)&th[n][kb];
        uint4 vl = *(uint4*)&tl[n][kb];
        *(uint4*)(hi + (size_t)(n0 + n) * Kd + k0 + kb) = vh;
        *(uint4*)(lo + (size_t)(n0 + n) * Kd + k0 + kb) = vl;
    }
}

// ---------------- merged RMSNorm+RoPE (Q,K) + V transpose ----------------
__global__ void __launch_bounds__(256) norm_rope_qkv(
    const float* __restrict__ QKVp, float* __restrict__ Kout, float* __restrict__ Vout,
    bf16* __restrict__ Qhi, bf16* __restrict__ Qlo,
    bf16* __restrict__ Khi, bf16* __restrict__ Klo,
    bf16* __restrict__ Vthi, bf16* __restrict__ Vtlo,
    const float* __restrict__ q_scale, const float* __restrict__ k_scale,
    const float* __restrict__ cosb, const float* __restrict__ sinb, float scl)
{
    int tid = threadIdx.x;
    int hh = blockIdx.y;

    if (hh >= NH + NKV) {
        __shared__ float tile[32][33];
        int kv = hh - (NH + NKV);
        int bx = blockIdx.x;
        int t0 = (bx & 63) * 32, d0 = (bx >> 6) * 32;
        int tx = tid & 31, ty = tid >> 5;
        const float* Vp = QKVp + QDIM + KVDIM;
#pragma unroll
        for (int j = 0; j < 32; j += 8) {
            int t = t0 + ty + j;
            float v = Vp[(size_t)t * QKV + kv * HD + d0 + tx];
            tile[ty + j][tx] = v;
            Vout[((size_t)kv * SEQ + t) * HD + d0 + tx] = v;
        }
        __syncthreads();
#pragma unroll
        for (int j = 0; j < 32; j += 8) {
            int d = d0 + ty + j, t = t0 + tx;
            float v = tile[tx][ty + j];
            size_t off = ((size_t)kv * HD + d) * SEQ + t;
            bf16 h = __float2bfloat16_rn(v);
            Vthi[off] = h;
            Vtlo[off] = __float2bfloat16_rn(v - __bfloat162float(h));
        }
        return;
    }

    int wid = tid >> 5, lane = tid & 31;
    int t = blockIdx.x * 8 + wid;
    int d = lane * 2;

    const float* scale;
    const float* base;
    bf16 *outh, *outl;
    float* outf = nullptr;
    size_t ob;
    float premul;
    if (hh < NH) {
        scale = q_scale; premul = scl;
        base = QKVp + (size_t)t * QKV + (size_t)hh * HD;
        outh = Qhi; outl = Qlo;
        ob = (size_t)t * QDIM + (size_t)hh * HD;
    } else {
        int h = hh - NH;
        scale = k_scale; premul = 1.0f;
        base = QKVp + (size_t)t * QKV + QDIM + (size_t)h * HD;
        outh = Khi; outl = Klo;
        outf = Kout;
        ob = (size_t)t * HD + (size_t)h * SEQ * HD;
    }

    float2 a = *(const float2*)(base + d);
    float2 b = *(const float2*)(base + d + 64);
    float ssq = a.x * a.x + a.y * a.y + b.x * b.x + b.y * b.y;
#pragma unroll
    for (int s = 16; s > 0; s >>= 1) ssq += __shfl_xor_sync(0xffffffffu, ssq, s);
    float rms = rsqrtf(ssq * (1.0f / 128.0f) + 1e-6f);
    float2 n1 = *(const float2*)(scale + d);
    float2 n2 = *(const float2*)(scale + d + 64);
    float a0 = a.x * rms * n1.x, a1 = a.y * rms * n1.y;
    float b0 = b.x * rms * n2.x, b1 = b.y * rms * n2.y;
    size_t cb = (size_t)t * HD;
    float2 c1 = *(const float2*)(cosb + cb + d);
    float2 s1 = *(const float2*)(sinb + cb + d);
    float2 c2 = *(const float2*)(cosb + cb + d + 64);
    float2 s2 = *(const float2*)(sinb + cb + d + 64);
    float o10 = (a0 * c1.x - b0 * s1.x) * premul;
    float o11 = (a1 * c1.y - b1 * s1.y) * premul;
    float o20 = (b0 * c2.x + a0 * s2.x) * premul;
    float o21 = (b1 * c2.y + a1 * s2.y) * premul;
    st_hl(outh, outl, ob + d,      o10, o11);
    st_hl(outh, outl, ob + d + 64, o20, o21);
    if (outf) {
        *(float2*)(outf + ob + d)      = make_float2(o10, o11);
        *(float2*)(outf + ob + d + 64) = make_float2(o20, o21);
    }
}

// ---------------- launch ----------------
extern "C" void kernel_launch(void* const* d_in, const int* in_sizes, int n_in,
                              void* d_out, int out_size)
{
    const float* x       = (const float*)d_in[0];
    const float* Wq      = (const float*)d_in[1];
    const float* Wk      = (const float*)d_in[2];
    const float* Wv      = (const float*)d_in[3];
    const float* Wo      = (const float*)d_in[4];
    const float* q_scale = (const float*)d_in[5];
    const float* k_scale = (const float*)d_in[6];
    const float* cosb    = (const float*)d_in[7];
    const float* sinb    = (const float*)d_in[8];

    float* out  = (float*)d_out;
    float* Kout = out  + (size_t)SEQ * DIN;
    float* Vout = Kout + (size_t)NKV * SEQ * HD;

    bf16 *xhi, *xlo, *Wqkvh, *Wqkvl, *Woh, *Wol;
    bf16 *Qhi, *Qlo, *Khi, *Klo, *Vthi, *Vtlo, *ctxh, *ctxl;
    float* QKVp;
    cudaGetSymbolAddress((void**)&xhi, g_xhi);     cudaGetSymbolAddress((void**)&xlo, g_xlo);
    cudaGetSymbolAddress((void**)&Wqkvh, g_Wqkvh); cudaGetSymbolAddress((void**)&Wqkvl, g_Wqkvl);
    cudaGetSymbolAddress((void**)&Woh, g_Woh);     cudaGetSymbolAddress((void**)&Wol, g_Wol);
    cudaGetSymbolAddress((void**)&QKVp, g_QKVp);
    cudaGetSymbolAddress((void**)&Qhi, g_Qhi);     cudaGetSymbolAddress((void**)&Qlo, g_Qlo);
    cudaGetSymbolAddress((void**)&Khi, g_Khi);     cudaGetSymbolAddress((void**)&Klo, g_Klo);
    cudaGetSymbolAddress((void**)&Vthi, g_Vthi);   cudaGetSymbolAddress((void**)&Vtlo, g_Vtlo);
    cudaGetSymbolAddress((void**)&ctxh, g_ctxh);   cudaGetSymbolAddress((void**)&ctxl, g_ctxl);

    const int SMEM = 3 * 32768;           // gemm: 98304
    const int FSMEM = 65536 + 2 * 65536;  // flash: 196608
    cudaFuncSetAttribute(gemm_bf3, cudaFuncAttributeMaxDynamicSharedMemorySize, SMEM);
    cudaFuncSetAttribute(flash_kernel, cudaFuncAttributeMaxDynamicSharedMemorySize, FSMEM);

    dim3 blk(128);
    const float scl = 0.08838834764831845f;   // 1/sqrt(128)

    // launch 1: all input conversions
    convert_all<<<6144, 256>>>(x, Wq, Wk, Wv, Wo, xhi, xlo, Wqkvh, Wqkvl, Woh, Wol);

    // launch 2: merged QKV projection -> QKVp fp32 [2048][6144]
    gemm_bf3<<<dim3(QKV / BN, SEQ / BM), blk, SMEM>>>(
        xhi, xlo, Wqkvh, Wqkvl, QKVp, nullptr, nullptr, DIN, DIN, QKV, DIN);

    // launch 3: norm/rope (Q,K) + V transpose
    norm_rope_qkv<<<dim3(SEQ / 8, NH + 2 * NKV), 256>>>(
        QKVp, Kout, Vout, Qhi, Qlo, Khi, Klo, Vthi, Vtlo,
        q_scale, k_scale, cosb, sinb, scl);

    // launch 4: fused attention -> ctx hi/lo
    flash_kernel<<<dim3(16, NH), 256, FSMEM>>>(Qhi, Qlo, Khi, Klo, Vthi, Vtlo, ctxh, ctxl);

    // launch 5: output projection -> out fp32
    gemm_bf3<<<dim3(DIN / BN, SEQ / BM), blk, SMEM>>>(
        ctxh, ctxl, Woh, Wol, out, nullptr, nullptr, QDIM, QDIM, DIN, QDIM);
}

// round 17
// speedup vs baseline: 1.0301x; 1.0094x over previous
#include <cuda_runtime.h>
#include <cuda_bf16.h>
#include <cstdint>

#define SEQ 2048
#define DIN 2048
#define NH 32
#define NKV 8
#define HD 128
#define QDIM 4096
#define KVDIM 1024
#define QKV (QDIM + 2 * KVDIM)   // 6144

typedef __nv_bfloat16 bf16;
typedef __nv_bfloat162 bf162;

#define BM 128
#define BN 128
#define BK 32

// ---------------- static scratch (no allocs allowed) ----------------
__device__ bf16 g_xhi[(size_t)SEQ * DIN];
__device__ bf16 g_xlo[(size_t)SEQ * DIN];
__device__ bf16 g_Wqkvh[(size_t)QKV * DIN], g_Wqkvl[(size_t)QKV * DIN];
__device__ bf16 g_Woh[(size_t)DIN * QDIM],  g_Wol[(size_t)DIN * QDIM];
__device__ float g_QKVp[(size_t)SEQ * QKV];
__device__ bf16 g_Qhi[(size_t)SEQ * QDIM], g_Qlo[(size_t)SEQ * QDIM];
__device__ bf16 g_Khi[(size_t)NKV * SEQ * HD], g_Klo[(size_t)NKV * SEQ * HD];
__device__ bf16 g_Vthi[(size_t)NKV * HD * SEQ], g_Vtlo[(size_t)NKV * HD * SEQ];
__device__ bf16 g_ctxh[(size_t)SEQ * QDIM], g_ctxl[(size_t)SEQ * QDIM];

// ---------------- helpers ----------------
__device__ __forceinline__ uint32_t smem_u32(const void* p) {
    uint32_t a;
    asm("{ .reg .u64 t; cvta.to.shared.u64 t, %1; cvt.u32.u64 %0, t; }" : "=r"(a) : "l"(p));
    return a;
}
#define SWZ64(o) ((o) ^ ((((o) >> 7) & 3u) << 4))

#define CP16(dst, src) asm volatile("cp.async.cg.shared.global [%0], [%1], 16;" :: "r"(dst), "l"(src))
#define CP_COMMIT()    asm volatile("cp.async.commit_group;" ::: "memory")
#define CP_WAIT1()     asm volatile("cp.async.wait_group 1;" ::: "memory")
#define CP_WAIT0()     asm volatile("cp.async.wait_group 0;" ::: "memory")

__device__ __forceinline__ void ldmx4(uint32_t* f, uint32_t addr) {
    asm volatile("ldmatrix.sync.aligned.m8n8.x4.shared.b16 {%0,%1,%2,%3}, [%4];"
        : "=r"(f[0]), "=r"(f[1]), "=r"(f[2]), "=r"(f[3]) : "r"(addr));
}
__device__ __forceinline__ void mma16816(float* d, const uint32_t* a, const uint32_t* b) {
    asm volatile("mma.sync.aligned.m16n8k16.row.col.f32.bf16.bf16.f32 "
        "{%0,%1,%2,%3}, {%4,%5,%6,%7}, {%8,%9}, {%0,%1,%2,%3};"
        : "+f"(d[0]), "+f"(d[1]), "+f"(d[2]), "+f"(d[3])
        : "r"(a[0]), "r"(a[1]), "r"(a[2]), "r"(a[3]), "r"(b[0]), "r"(b[1]));
}
__device__ __forceinline__ void st_hl(bf16* hi, bf16* lo, size_t off, float a, float b) {
    bf162 h = __floats2bfloat162_rn(a, b);
    float2 f = __bfloat1622float2(h);
    bf162 l = __floats2bfloat162_rn(a - f.x, b - f.y);
    *(bf162*)(hi + off) = h;
    *(bf162*)(lo + off) = l;
}
__device__ __forceinline__ void pack_hl(float x, float y, uint32_t& hp, uint32_t& lp) {
    bf162 h = __floats2bfloat162_rn(x, y);
    float2 f = __bfloat1622float2(h);
    bf162 l = __floats2bfloat162_rn(x - f.x, y - f.y);
    hp = *(uint32_t*)&h;
    lp = *(uint32_t*)&l;
}

// ---------------- bf16x3 tensor GEMM (verified core, UNTOUCHED) ----------------
extern __shared__ char dsm[];
__global__ void __launch_bounds__(128, 2) gemm_bf3(
    const bf16* __restrict__ Ahi, const bf16* __restrict__ Alo,
    const bf16* __restrict__ Bhi, const bf16* __restrict__ Blo,
    float* __restrict__ C, bf16* __restrict__ Chi, bf16* __restrict__ Clo,
    int lda, int ldb, int ldc, int K)
{
    int row0 = blockIdx.y * BM, col0 = blockIdx.x * BN;
    size_t aoff = (size_t)row0 * lda;
    size_t boff = (size_t)col0 * ldb;
    Ahi += aoff; Alo += aoff; Bhi += boff; Blo += boff;
    size_t coff = (size_t)row0 * ldc + col0;
    int nch = K / BK;

    uint32_t sb = smem_u32(dsm);
    int tid = threadIdx.x;
    int lane = tid & 31, wid = tid >> 5;
    int wm = wid >> 1, wn = wid & 1;

    uint32_t smo[4];
    size_t gA[4], gB[4];
#pragma unroll
    for (int i = 0; i < 4; i++) {
        int id = tid + i * 128;
        int r = id >> 2, c = id & 3;
        smo[i] = SWZ64((uint32_t)(r * 64 + c * 16));
        gA[i] = (size_t)r * lda + c * 8;
        gB[i] = (size_t)r * ldb + c * 8;
    }

    float acc[4][8][4];
#pragma unroll
    for (int i = 0; i < 4; i++)
#pragma unroll
        for (int j = 0; j < 8; j++)
#pragma unroll
            for (int e = 0; e < 4; e++) acc[i][j][e] = 0.f;

#define ISSUE(ch, s) do {                                                  \
        uint32_t st_ = sb + (uint32_t)(s) * 32768u;                        \
        int k0_ = (ch) * BK;                                               \
        _Pragma("unroll")                                                  \
        for (int i_ = 0; i_ < 4; i_++) {                                   \
            CP16(st_ + smo[i_],          Ahi + gA[i_] + k0_);              \
            CP16(st_ + 8192  + smo[i_],  Alo + gA[i_] + k0_);              \
            CP16(st_ + 16384 + smo[i_],  Bhi + gB[i_] + k0_);              \
            CP16(st_ + 24576 + smo[i_],  Blo + gB[i_] + k0_);              \
        }                                                                  \
        CP_COMMIT();                                                       \
    } while (0)

    ISSUE(0, 0);
    if (nch > 1) ISSUE(1, 1);

    int a_r = lane & 15;
    int a_c = lane >> 4;
    int b_q = lane >> 3;
    int b_r = (b_q >> 1) * 8 + (lane & 7);
    int b_c = b_q & 1;

    for (int ch = 0; ch < nch; ch++) {
        if (ch + 1 < nch) CP_WAIT1(); else CP_WAIT0();
        __syncthreads();
        if (ch + 2 < nch) ISSUE(ch + 2, (ch + 2) % 3);

        uint32_t st = sb + (uint32_t)(ch % 3) * 32768u;
#pragma unroll
        for (int ks = 0; ks < 2; ks++) {
            uint32_t ah[4][4], al[4][4];
#pragma unroll
            for (int mf = 0; mf < 4; mf++) {
                int row = wm * 64 + mf * 16 + a_r;
                uint32_t off = SWZ64((uint32_t)(row * 64 + (ks * 2 + a_c) * 16));
                ldmx4(ah[mf], st + off);
                ldmx4(al[mf], st + 8192 + off);
            }
#pragma unroll
            for (int np = 0; np < 4; np++) {
                int row = wn * 64 + np * 16 + b_r;
                uint32_t off = SWZ64((uint32_t)(row * 64 + (ks * 2 + b_c) * 16));
                uint32_t bh4[4], bl4[4];
                ldmx4(bh4, st + 16384 + off);
                ldmx4(bl4, st + 24576 + off);
#pragma unroll
                for (int mf = 0; mf < 4; mf++) {
                    float* d0 = acc[mf][np * 2];
                    mma16816(d0, ah[mf], bh4);
                    mma16816(d0, ah[mf], bl4);
                    mma16816(d0, al[mf], bh4);
                    float* d1 = acc[mf][np * 2 + 1];
                    mma16816(d1, ah[mf], bh4 + 2);
                    mma16816(d1, ah[mf], bl4 + 2);
                    mma16816(d1, al[mf], bh4 + 2);
                }
            }
        }
        __syncthreads();
    }

    int g = lane >> 2, tg = lane & 3;
#pragma unroll
    for (int mf = 0; mf < 4; mf++)
#pragma unroll
        for (int nf = 0; nf < 8; nf++) {
            int rA = wm * 64 + mf * 16 + g;
            int cc = wn * 64 + nf * 8 + tg * 2;
            float* d = acc[mf][nf];
            if (C) {
                *(float2*)(C + coff + (size_t)rA * ldc + cc)       = make_float2(d[0], d[1]);
                *(float2*)(C + coff + (size_t)(rA + 8) * ldc + cc) = make_float2(d[2], d[3]);
            } else {
                st_hl(Chi, Clo, coff + (size_t)rA * ldc + cc,       d[0], d[1]);
                st_hl(Chi, Clo, coff + (size_t)(rA + 8) * ldc + cc, d[2], d[3]);
            }
        }
#undef ISSUE
}

// ---------------- fused flash attention v4: 3-stage KV, hoisted Q-hi, 1 sync/step
// |s_scaled| <= sqrt(128) ~ 11.32; fixed max M=13; row factor cancels in p/l.
// SMEM: [Qlo 0..32K) ; stages at 32K + s*64K (s=0..2): [Khi|Klo|Vhi|Vlo] 16K each.
#define SMAX 13.0f
#define ST0 32768u
__global__ void __launch_bounds__(256, 1) flash_kernel(
    const bf16* __restrict__ Qhi, const bf16* __restrict__ Qlo,
    const bf16* __restrict__ Khi, const bf16* __restrict__ Klo,
    const bf16* __restrict__ Vthi, const bf16* __restrict__ Vtlo,
    bf16* __restrict__ ctxh, bf16* __restrict__ ctxl)
{
    int qt = (int)gridDim.x - 1 - (int)blockIdx.x;   // big tiles first
    int h = blockIdx.y;
    int kv = h >> 2;
    int tid = threadIdx.x, lane = tid & 31, wid = tid >> 5;

    uint32_t sb = smem_u32(dsm);

    int a_r = lane & 15, a_c = lane >> 4;
    int b_q = lane >> 3, b_r = (b_q >> 1) * 8 + (lane & 7), b_c = b_q & 1;

    // ---- prologue: Qlo -> [0,32K), Qhi -> staging at [ST0, ST0+32K) ----
    {
        size_t qg = (size_t)(qt * 128) * QDIM + (size_t)h * HD;
#pragma unroll
        for (int i = 0; i < 16; i++) {
            int id = tid + i * 256;
            int hl = id >> 11, rem = id & 2047;
            int row = rem >> 4, c = rem & 15;
            int kc = c >> 2, cc = c & 3;
            uint32_t base = hl ? sb : (sb + ST0);      // lo -> 0, hi -> staging
            uint32_t dst = base + (uint32_t)(kc * 8192) +
                           SWZ64((uint32_t)(row * 64 + cc * 16));
            const bf16* src = (hl ? Qlo : Qhi) + qg + (size_t)row * QDIM + kc * 32 + cc * 8;
            CP16(dst, src);
        }
        CP_COMMIT();
    }
    CP_WAIT0();
    __syncthreads();

    // extract Q-hi fragments (loop-invariant) into registers
    uint32_t qh[8][4];
    {
        int row = wid * 16 + a_r;
#pragma unroll
        for (int kc = 0; kc < 4; kc++)
#pragma unroll
            for (int ks = 0; ks < 2; ks++) {
                uint32_t off = (uint32_t)(kc * 8192) +
                               SWZ64((uint32_t)(row * 64 + (ks * 2 + a_c) * 16));
                ldmx4(qh[kc * 2 + ks], sb + ST0 + off);
            }
    }
    __syncthreads();   // staging free -> becomes KV stage 0

#define KV_ISSUE(n, s) do {                                                     \
        uint32_t st_ = sb + ST0 + (uint32_t)(s) * 65536u;                       \
        int t0_ = (n) * 64;                                                     \
        _Pragma("unroll")                                                       \
        for (int i_ = 0; i_ < 8; i_++) {                                        \
            int id = tid + i_ * 256;                                            \
            int hl = id >> 10, rem = id & 1023;                                 \
            int row = rem >> 4, c = rem & 15;                                   \
            int kc = c >> 2, cc = c & 3;                                        \
            uint32_t dst = st_ + (uint32_t)(hl * 16384 + kc * 4096) +           \
                           SWZ64((uint32_t)(row * 64 + cc * 16));               \
            const bf16* src = (hl ? Klo : Khi) +                                \
                ((size_t)kv * SEQ + t0_ + row) * HD + kc * 32 + cc * 8;         \
            CP16(dst, src);                                                     \
        }                                                                       \
        _Pragma("unroll")                                                       \
        for (int i_ = 0; i_ < 8; i_++) {                                        \
            int id = tid + i_ * 256;                                            \
            int hl = id >> 10, rem = id & 1023;                                 \
            int row = rem >> 3, c = rem & 7;                                    \
            int tc = c >> 2, cc = c & 3;                                        \
            uint32_t dst = st_ + 32768u + (uint32_t)(hl * 16384 + tc * 8192) +  \
                           SWZ64((uint32_t)(row * 64 + cc * 16));               \
            const bf16* src = (hl ? Vtlo : Vthi) +                              \
                ((size_t)kv * HD + row) * SEQ + t0_ + tc * 32 + cc * 8;         \
            CP16(dst, src);                                                     \
        }                                                                       \
        CP_COMMIT();                                                            \
    } while (0)

    int nsteps = 2 * qt + 2;
    KV_ISSUE(0, 0);
    if (nsteps > 1) KV_ISSUE(1, 1);

    float o[16][4];
#pragma unroll
    for (int i = 0; i < 16; i++)
#pragma unroll
        for (int e = 0; e < 4; e++) o[i][e] = 0.f;
    float l0 = 0.f, l1 = 0.f;

    for (int n = 0; n < nsteps; n++) {
        if (n + 1 < nsteps) CP_WAIT1(); else CP_WAIT0();
        __syncthreads();                         // single barrier per step
        if (n + 2 < nsteps) KV_ISSUE(n + 2, (n + 2) % 3);

        uint32_t st = sb + ST0 + (uint32_t)(n % 3) * 65536u;

        float s[8][4];
#pragma unroll
        for (int i = 0; i < 8; i++)
#pragma unroll
            for (int e = 0; e < 4; e++) s[i][e] = 0.f;

#pragma unroll
        for (int kc = 0; kc < 4; kc++)
#pragma unroll
            for (int ks = 0; ks < 2; ks++) {
                uint32_t al[4];
                const uint32_t* ah = qh[kc * 2 + ks];
                {
                    int row = wid * 16 + a_r;
                    uint32_t off = (uint32_t)(kc * 8192) +
                                   SWZ64((uint32_t)(row * 64 + (ks * 2 + a_c) * 16));
                    ldmx4(al, sb + off);         // Q-lo from smem base 0
                }
#pragma unroll
                for (int np = 0; np < 4; np++) {
                    int row = np * 16 + b_r;
                    uint32_t off = (uint32_t)(kc * 4096) +
                                   SWZ64((uint32_t)(row * 64 + (ks * 2 + b_c) * 16));
                    uint32_t bh4[4], bl4[4];
                    ldmx4(bh4, st + off);
                    ldmx4(bl4, st + 16384u + off);
                    float* d0 = s[np * 2];
                    float* d1 = s[np * 2 + 1];
                    mma16816(d0, ah, bh4);
                    mma16816(d1, ah, bh4 + 2);
                    mma16816(d0, ah, bl4);
                    mma16816(d1, ah, bl4 + 2);
                    mma16816(d0, al, bh4);
                    mma16816(d1, al, bh4 + 2);
                }
            }

        if (n >= nsteps - 2) {
            int row0 = qt * 128 + wid * 16 + (lane >> 2);
            int colb = n * 64 + (lane & 3) * 2;
#pragma unroll
            for (int nf = 0; nf < 8; nf++) {
                int c0 = colb + nf * 8;
                if (c0 > row0)         s[nf][0] = -1e30f;
                if (c0 + 1 > row0)     s[nf][1] = -1e30f;
                if (c0 > row0 + 8)     s[nf][2] = -1e30f;
                if (c0 + 1 > row0 + 8) s[nf][3] = -1e30f;
            }
        }

        // ---- static-max softmax ----
#pragma unroll
        for (int nf = 0; nf < 8; nf++) {
            s[nf][0] = __expf(s[nf][0] - SMAX);
            s[nf][1] = __expf(s[nf][1] - SMAX);
            s[nf][2] = __expf(s[nf][2] - SMAX);
            s[nf][3] = __expf(s[nf][3] - SMAX);
            l0 += s[nf][0] + s[nf][1];
            l1 += s[nf][2] + s[nf][3];
        }

        // ---- O += P V (bf16x3), interleaved d0/d1 ----
#pragma unroll
        for (int kb = 0; kb < 4; kb++) {
            uint32_t ph[4], pl[4];
            pack_hl(s[2 * kb][0],     s[2 * kb][1],     ph[0], pl[0]);
            pack_hl(s[2 * kb][2],     s[2 * kb][3],     ph[1], pl[1]);
            pack_hl(s[2 * kb + 1][0], s[2 * kb + 1][1], ph[2], pl[2]);
            pack_hl(s[2 * kb + 1][2], s[2 * kb + 1][3], ph[3], pl[3]);
            uint32_t vbase = 32768u + (uint32_t)((kb >> 1) * 8192);
            int kcol = ((kb & 1) * 2 + b_c) * 16;
#pragma unroll
            for (int nb = 0; nb < 8; nb++) {
                int row = nb * 16 + b_r;
                uint32_t off = vbase + SWZ64((uint32_t)(row * 64 + kcol));
                uint32_t vh4[4], vl4[4];
                ldmx4(vh4, st + off);
                ldmx4(vl4, st + 16384u + off);
                float* d0 = o[nb * 2];
                float* d1 = o[nb * 2 + 1];
                mma16816(d0, ph, vh4);
                mma16816(d1, ph, vh4 + 2);
                mma16816(d0, pl, vh4);
                mma16816(d1, pl, vh4 + 2);
                mma16816(d0, ph, vl4);
                mma16816(d1, ph, vl4 + 2);
            }
        }
        // no bottom barrier: next-step issue protected by top barrier (3 stages)
    }

    l0 += __shfl_xor_sync(0xffffffffu, l0, 1);
    l0 += __shfl_xor_sync(0xffffffffu, l0, 2);
    l1 += __shfl_xor_sync(0xffffffffu, l1, 1);
    l1 += __shfl_xor_sync(0xffffffffu, l1, 2);
    float inv0 = 1.f / l0, inv1 = 1.f / l1;
    int row0 = qt * 128 + wid * 16 + (lane >> 2);
    size_t base = (size_t)row0 * QDIM + (size_t)h * HD;
#pragma unroll
    for (int nf = 0; nf < 16; nf++) {
        int col = nf * 8 + (lane & 3) * 2;
        st_hl(ctxh, ctxl, base + col,             o[nf][0] * inv0, o[nf][1] * inv0);
        st_hl(ctxh, ctxl, base + 8 * QDIM + col,  o[nf][2] * inv1, o[nf][3] * inv1);
    }
#undef KV_ISSUE
}

// ---------------- unified converter: weights (transpose) + x (elementwise) -----
__global__ void __launch_bounds__(256) convert_all(
    const float* __restrict__ x,
    const float* __restrict__ Wq, const float* __restrict__ Wk,
    const float* __restrict__ Wv, const float* __restrict__ Wo,
    bf16* __restrict__ xhi, bf16* __restrict__ xlo,
    bf16* __restrict__ Wqkvh, bf16* __restrict__ Wqkvl,
    bf16* __restrict__ Woh, bf16* __restrict__ Wol)
{
    __shared__ bf16 th[64][72];
    __shared__ bf16 tl[64][72];
    int t = blockIdx.x;
    int tid = threadIdx.x;

    if (t >= 5120) {
        size_t base4 = (size_t)(t - 5120) * 1024;
#pragma unroll
        for (int i = 0; i < 4; i++) {
            size_t idx = base4 + tid + i * 256;
            float4 v = ((const float4*)x)[idx];
            bf162 h01 = __floats2bfloat162_rn(v.x, v.y);
            bf162 h23 = __floats2bfloat162_rn(v.z, v.w);
            float2 f01 = __bfloat1622float2(h01);
            float2 f23 = __bfloat1622float2(h23);
            ((bf162*)xhi)[2 * idx]     = h01;
            ((bf162*)xhi)[2 * idx + 1] = h23;
            ((bf162*)xlo)[2 * idx]     = __floats2bfloat162_rn(v.x - f01.x, v.y - f01.y);
            ((bf162*)xlo)[2 * idx + 1] = __floats2bfloat162_rn(v.z - f23.x, v.w - f23.y);
        }
        return;
    }

    const float* W;
    bf16 *hi, *lo;
    int Kd, Nd, idx;
    if (t < 2048)      { W = Wq; hi = Wqkvh;                        lo = Wqkvl;                        Kd = DIN;  Nd = QDIM;  idx = t; }
    else if (t < 2560) { W = Wk; hi = Wqkvh + (size_t)QDIM * DIN;   lo = Wqkvl + (size_t)QDIM * DIN;   Kd = DIN;  Nd = KVDIM; idx = t - 2048; }
    else if (t < 3072) { W = Wv; hi = Wqkvh + (size_t)(QDIM + KVDIM) * DIN; lo = Wqkvl + (size_t)(QDIM + KVDIM) * DIN; Kd = DIN; Nd = KVDIM; idx = t - 2560; }
    else               { W = Wo; hi = Woh;                          lo = Wol;                          Kd = QDIM; Nd = DIN;   idx = t - 3072; }
    int ntn = Nd >> 6;
    int n0 = (idx % ntn) * 64, k0 = (idx / ntn) * 64;
#pragma unroll
    for (int i = 0; i < 4; i++) {
        int id = tid + i * 256;
        int r = id >> 4, c = (id & 15) * 4;
        float4 v = *(const float4*)(W + (size_t)(k0 + r) * Nd + n0 + c);
        float a[4] = {v.x, v.y, v.z, v.w};
#pragma unroll
        for (int j = 0; j < 4; j++) {
            bf16 h = __float2bfloat16_rn(a[j]);
            th[c + j][r] = h;
            tl[c + j][r] = __float2bfloat16_rn(a[j] - __bfloat162float(h));
        }
    }
    __syncthreads();
#pragma unroll
    for (int i = 0; i < 2; i++) {
        int id = tid + i * 256;
        int n = id >> 3, kb = (id & 7) * 8;
        uint4 vh = *(uint4*)&th[n][kb];
        uint4 vl = *(uint4*)&tl[n][kb];
        *(uint4*)(hi + (size_t)(n0 + n) * Kd + k0 + kb) = vh;
        *(uint4*)(lo + (size_t)(n0 + n) * Kd + k0 + kb) = vl;
    }
}

// ---------------- merged RMSNorm+RoPE (Q,K) + V transpose ----------------
__global__ void __launch_bounds__(256) norm_rope_qkv(
    const float* __restrict__ QKVp, float* __restrict__ Kout, float* __restrict__ Vout,
    bf16* __restrict__ Qhi, bf16* __restrict__ Qlo,
    bf16* __restrict__ Khi, bf16* __restrict__ Klo,
    bf16* __restrict__ Vthi, bf16* __restrict__ Vtlo,
    const float* __restrict__ q_scale, const float* __restrict__ k_scale,
    const float* __restrict__ cosb, const float* __restrict__ sinb, float scl)
{
    int tid = threadIdx.x;
    int hh = blockIdx.y;

    if (hh >= NH + NKV) {
        __shared__ float tile[32][33];
        int kv = hh - (NH + NKV);
        int bx = blockIdx.x;
        int t0 = (bx & 63) * 32, d0 = (bx >> 6) * 32;
        int tx = tid & 31, ty = tid >> 5;
        const float* Vp = QKVp + QDIM + KVDIM;
#pragma unroll
        for (int j = 0; j < 32; j += 8) {
            int t = t0 + ty + j;
            float v = Vp[(size_t)t * QKV + kv * HD + d0 + tx];
            tile[ty + j][tx] = v;
            Vout[((size_t)kv * SEQ + t) * HD + d0 + tx] = v;
        }
        __syncthreads();
#pragma unroll
        for (int j = 0; j < 32; j += 8) {
            int d = d0 + ty + j, t = t0 + tx;
            float v = tile[tx][ty + j];
            size_t off = ((size_t)kv * HD + d) * SEQ + t;
            bf16 h = __float2bfloat16_rn(v);
            Vthi[off] = h;
            Vtlo[off] = __float2bfloat16_rn(v - __bfloat162float(h));
        }
        return;
    }

    int wid = tid >> 5, lane = tid & 31;
    int t = blockIdx.x * 8 + wid;
    int d = lane * 2;

    const float* scale;
    const float* base;
    bf16 *outh, *outl;
    float* outf = nullptr;
    size_t ob;
    float premul;
    if (hh < NH) {
        scale = q_scale; premul = scl;
        base = QKVp + (size_t)t * QKV + (size_t)hh * HD;
        outh = Qhi; outl = Qlo;
        ob = (size_t)t * QDIM + (size_t)hh * HD;
    } else {
        int h = hh - NH;
        scale = k_scale; premul = 1.0f;
        base = QKVp + (size_t)t * QKV + QDIM + (size_t)h * HD;
        outh = Khi; outl = Klo;
        outf = Kout;
        ob = (size_t)t * HD + (size_t)h * SEQ * HD;
    }

    float2 a = *(const float2*)(base + d);
    float2 b = *(const float2*)(base + d + 64);
    float ssq = a.x * a.x + a.y * a.y + b.x * b.x + b.y * b.y;
#pragma unroll
    for (int s = 16; s > 0; s >>= 1) ssq += __shfl_xor_sync(0xffffffffu, ssq, s);
    float rms = rsqrtf(ssq * (1.0f / 128.0f) + 1e-6f);
    float2 n1 = *(const float2*)(scale + d);
    float2 n2 = *(const float2*)(scale + d + 64);
    float a0 = a.x * rms * n1.x, a1 = a.y * rms * n1.y;
    float b0 = b.x * rms * n2.x, b1 = b.y * rms * n2.y;
    size_t cb = (size_t)t * HD;
    float2 c1 = *(const float2*)(cosb + cb + d);
    float2 s1 = *(const float2*)(sinb + cb + d);
    float2 c2 = *(const float2*)(cosb + cb + d + 64);
    float2 s2 = *(const float2*)(sinb + cb + d + 64);
    float o10 = (a0 * c1.x - b0 * s1.x) * premul;
    float o11 = (a1 * c1.y - b1 * s1.y) * premul;
    float o20 = (b0 * c2.x + a0 * s2.x) * premul;
    float o21 = (b1 * c2.y + a1 * s2.y) * premul;
    st_hl(outh, outl, ob + d,      o10, o11);
    st_hl(outh, outl, ob + d + 64, o20, o21);
    if (outf) {
        *(float2*)(outf + ob + d)      = make_float2(o10, o11);
        *(float2*)(outf + ob + d + 64) = make_float2(o20, o21);
    }
}

// ---------------- launch ----------------
extern "C" void kernel_launch(void* const* d_in, const int* in_sizes, int n_in,
                              void* d_out, int out_size)
{
    const float* x       = (const float*)d_in[0];
    const float* Wq      = (const float*)d_in[1];
    const float* Wk      = (const float*)d_in[2];
    const float* Wv      = (const float*)d_in[3];
    const float* Wo      = (const float*)d_in[4];
    const float* q_scale = (const float*)d_in[5];
    const float* k_scale = (const float*)d_in[6];
    const float* cosb    = (const float*)d_in[7];
    const float* sinb    = (const float*)d_in[8];

    float* out  = (float*)d_out;
    float* Kout = out  + (size_t)SEQ * DIN;
    float* Vout = Kout + (size_t)NKV * SEQ * HD;

    bf16 *xhi, *xlo, *Wqkvh, *Wqkvl, *Woh, *Wol;
    bf16 *Qhi, *Qlo, *Khi, *Klo, *Vthi, *Vtlo, *ctxh, *ctxl;
    float* QKVp;
    cudaGetSymbolAddress((void**)&xhi, g_xhi);     cudaGetSymbolAddress((void**)&xlo, g_xlo);
    cudaGetSymbolAddress((void**)&Wqkvh, g_Wqkvh); cudaGetSymbolAddress((void**)&Wqkvl, g_Wqkvl);
    cudaGetSymbolAddress((void**)&Woh, g_Woh);     cudaGetSymbolAddress((void**)&Wol, g_Wol);
    cudaGetSymbolAddress((void**)&QKVp, g_QKVp);
    cudaGetSymbolAddress((void**)&Qhi, g_Qhi);     cudaGetSymbolAddress((void**)&Qlo, g_Qlo);
    cudaGetSymbolAddress((void**)&Khi, g_Khi);     cudaGetSymbolAddress((void**)&Klo, g_Klo);
    cudaGetSymbolAddress((void**)&Vthi, g_Vthi);   cudaGetSymbolAddress((void**)&Vtlo, g_Vtlo);
    cudaGetSymbolAddress((void**)&ctxh, g_ctxh);   cudaGetSymbolAddress((void**)&ctxl, g_ctxl);

    const int SMEM = 3 * 32768;              // gemm: 98304
    const int FSMEM = 32768 + 3 * 65536;     // flash: 229376 (Qlo + 3 KV stages)
    cudaFuncSetAttribute(gemm_bf3, cudaFuncAttributeMaxDynamicSharedMemorySize, SMEM);
    cudaFuncSetAttribute(flash_kernel, cudaFuncAttributeMaxDynamicSharedMemorySize, FSMEM);

    dim3 blk(128);
    const float scl = 0.08838834764831845f;   // 1/sqrt(128)

    // launch 1: all input conversions
    convert_all<<<6144, 256>>>(x, Wq, Wk, Wv, Wo, xhi, xlo, Wqkvh, Wqkvl, Woh, Wol);

    // launch 2: merged QKV projection -> QKVp fp32 [2048][6144]
    gemm_bf3<<<dim3(QKV / BN, SEQ / BM), blk, SMEM>>>(
        xhi, xlo, Wqkvh, Wqkvl, QKVp, nullptr, nullptr, DIN, DIN, QKV, DIN);

    // launch 3: norm/rope (Q,K) + V transpose
    norm_rope_qkv<<<dim3(SEQ / 8, NH + 2 * NKV), 256>>>(
        QKVp, Kout, Vout, Qhi, Qlo, Khi, Klo, Vthi, Vtlo,
        q_scale, k_scale, cosb, sinb, scl);

    // launch 4: fused attention -> ctx hi/lo
    flash_kernel<<<dim3(16, NH), 256, FSMEM>>>(Qhi, Qlo, Khi, Klo, Vthi, Vtlo, ctxh, ctxl);

    // launch 5: output projection -> out fp32
    gemm_bf3<<<dim3(DIN / BN, SEQ / BM), blk, SMEM>>>(
        ctxh, ctxl, Woh, Wol, out, nullptr, nullptr, QDIM, QDIM, DIN, QDIM);
}